// round 3
// baseline (speedup 1.0000x reference)
#include <cuda_runtime.h>

// ---------------------------------------------------------------------------
// MetricPredictor: 2-layer GCN (degree features) + sum-pool + 2-layer MLP
// CSR-gather formulation; MLP-widened atomics; 64-node GEMM tiles.
// ---------------------------------------------------------------------------

#define MAXN 16384
#define MAXE 524288
#define NTHREADS 256
#define FULLMASK 0xFFFFFFFFu

__device__ __align__(16) int   g_incnt[MAXN];
__device__ __align__(16) int   g_outcnt[MAXN];
__device__ __align__(16) int   g_rowoff[MAXN + 1];
__device__ __align__(16) int   g_cursor[MAXN];
__device__ __align__(16) int   g_csrc[MAXE];
__device__ __align__(16) float g_h1[MAXN * 128];
__device__ __align__(16) float g_agg2[MAXN * 128];
__device__ __align__(16) float g_ge[256];

__device__ __forceinline__ int get_N(const int* np) {
    return np ? __ldg(np) : 10000;
}

// ---------------------------------------------------------------------------
__global__ void k_zero() {
    int i = blockIdx.x * blockDim.x + threadIdx.x;
    int stride = gridDim.x * blockDim.x;
    for (int j = i; j < MAXN; j += stride) { g_incnt[j] = 0; g_outcnt[j] = 0; }
    if (i < 256) g_ge[i] = 0.f;
}

// degree counts, 4 edges/thread (independent atomics -> MLP=4..8)
__global__ void k_count(const int* __restrict__ src, const int* __restrict__ dst, int E) {
    int e0 = 4 * (blockIdx.x * blockDim.x + threadIdx.x);
    if (e0 + 3 < E) {
        int4 s = *(const int4*)&src[e0];
        int4 d = *(const int4*)&dst[e0];
        atomicAdd(&g_incnt[d.x], 1);
        atomicAdd(&g_incnt[d.y], 1);
        atomicAdd(&g_incnt[d.z], 1);
        atomicAdd(&g_incnt[d.w], 1);
        atomicAdd(&g_outcnt[s.x], 1);
        atomicAdd(&g_outcnt[s.y], 1);
        atomicAdd(&g_outcnt[s.z], 1);
        atomicAdd(&g_outcnt[s.w], 1);
    } else {
        for (int e = e0; e < E; e++) {
            atomicAdd(&g_incnt[dst[e]], 1);
            atomicAdd(&g_outcnt[src[e]], 1);
        }
    }
}

// exclusive scan of g_incnt -> g_rowoff, g_cursor (single block)
__global__ void __launch_bounds__(1024) k_scan() {
    __shared__ int s_part[1024];
    const int CH = MAXN / 1024;  // 16
    int t = threadIdx.x;
    int base = t * CH;
    int loc[CH];
    int sum = 0;
#pragma unroll
    for (int i = 0; i < CH; i++) { loc[i] = sum; sum += g_incnt[base + i]; }
    s_part[t] = sum;
    __syncthreads();
    for (int off = 1; off < 1024; off <<= 1) {
        int v = (t >= off) ? s_part[t - off] : 0;
        __syncthreads();
        s_part[t] += v;
        __syncthreads();
    }
    int pre = (t > 0) ? s_part[t - 1] : 0;
#pragma unroll
    for (int i = 0; i < CH; i++) {
        int o = pre + loc[i];
        g_rowoff[base + i] = o;
        g_cursor[base + i] = o;
    }
    if (t == 1023) g_rowoff[MAXN] = s_part[1023];
}

// fill CSR, 4 edges/thread
__global__ void k_fill(const int* __restrict__ src, const int* __restrict__ dst, int E) {
    int e0 = 4 * (blockIdx.x * blockDim.x + threadIdx.x);
    if (e0 + 3 < E) {
        int4 s = *(const int4*)&src[e0];
        int4 d = *(const int4*)&dst[e0];
        int p0 = atomicAdd(&g_cursor[d.x], 1);
        int p1 = atomicAdd(&g_cursor[d.y], 1);
        int p2 = atomicAdd(&g_cursor[d.z], 1);
        int p3 = atomicAdd(&g_cursor[d.w], 1);
        g_csrc[p0] = s.x;
        g_csrc[p1] = s.y;
        g_csrc[p2] = s.z;
        g_csrc[p3] = s.w;
    } else {
        for (int e = e0; e < E; e++) {
            int pos = atomicAdd(&g_cursor[dst[e]], 1);
            g_csrc[pos] = src[e];
        }
    }
}

// fused: agg1 (gather of [in_deg,out_deg]) + h1 = relu(agg1@W1+b1), warp/node
__global__ void k_l1(const float* __restrict__ W1, const float* __restrict__ b1,
                     const int* __restrict__ np) {
    int N = get_N(np);
    int w = (blockIdx.x * blockDim.x + threadIdx.x) >> 5;
    if (w >= N) return;
    int lane = threadIdx.x & 31;
    int beg = g_rowoff[w];
    int end = beg + g_incnt[w];
    float a0 = 0.f, a1 = 0.f;
    for (int j = beg + lane; j < end; j += 32) {
        int s = g_csrc[j];
        a0 += (float)__ldg(&g_incnt[s]);
        a1 += (float)__ldg(&g_outcnt[s]);
    }
#pragma unroll
    for (int off = 16; off >= 1; off >>= 1) {
        a0 += __shfl_down_sync(FULLMASK, a0, off);
        a1 += __shfl_down_sync(FULLMASK, a1, off);
    }
    a0 = __shfl_sync(FULLMASK, a0, 0);
    a1 = __shfl_sync(FULLMASK, a1, 0);
    float4 r;
    int j = lane * 4;
    r.x = fmaxf(fmaf(a0, __ldg(&W1[j + 0]), fmaf(a1, __ldg(&W1[128 + j + 0]), __ldg(&b1[j + 0]))), 0.f);
    r.y = fmaxf(fmaf(a0, __ldg(&W1[j + 1]), fmaf(a1, __ldg(&W1[128 + j + 1]), __ldg(&b1[j + 1]))), 0.f);
    r.z = fmaxf(fmaf(a0, __ldg(&W1[j + 2]), fmaf(a1, __ldg(&W1[128 + j + 2]), __ldg(&b1[j + 2]))), 0.f);
    r.w = fmaxf(fmaf(a0, __ldg(&W1[j + 3]), fmaf(a1, __ldg(&W1[128 + j + 3]), __ldg(&b1[j + 3]))), 0.f);
    *(float4*)&g_h1[w * 128 + j] = r;
}

// agg2 = segment_sum(h1[src], dst); warp/node gather-reduce, 4-way ILP unroll
__global__ void k_agg2(const int* __restrict__ np) {
    int N = get_N(np);
    int w = (blockIdx.x * blockDim.x + threadIdx.x) >> 5;
    if (w >= N) return;
    int lane = threadIdx.x & 31;
    int beg = g_rowoff[w];
    int end = beg + g_incnt[w];
    float4 acc0 = make_float4(0.f, 0.f, 0.f, 0.f);
    float4 acc1 = acc0, acc2 = acc0, acc3 = acc0;
    int col = lane * 4;
    for (int j0 = beg; j0 < end; j0 += 32) {
        int m = end - j0; if (m > 32) m = 32;
        int sl = (lane < m) ? g_csrc[j0 + lane] : 0;
        int k = 0;
        for (; k + 4 <= m; k += 4) {
            int s0 = __shfl_sync(FULLMASK, sl, k + 0);
            int s1 = __shfl_sync(FULLMASK, sl, k + 1);
            int s2 = __shfl_sync(FULLMASK, sl, k + 2);
            int s3 = __shfl_sync(FULLMASK, sl, k + 3);
            float4 v0 = *(const float4*)&g_h1[s0 * 128 + col];
            float4 v1 = *(const float4*)&g_h1[s1 * 128 + col];
            float4 v2 = *(const float4*)&g_h1[s2 * 128 + col];
            float4 v3 = *(const float4*)&g_h1[s3 * 128 + col];
            acc0.x += v0.x; acc0.y += v0.y; acc0.z += v0.z; acc0.w += v0.w;
            acc1.x += v1.x; acc1.y += v1.y; acc1.z += v1.z; acc1.w += v1.w;
            acc2.x += v2.x; acc2.y += v2.y; acc2.z += v2.z; acc2.w += v2.w;
            acc3.x += v3.x; acc3.y += v3.y; acc3.z += v3.z; acc3.w += v3.w;
        }
        for (; k < m; k++) {
            int s = __shfl_sync(FULLMASK, sl, k);
            float4 v = *(const float4*)&g_h1[s * 128 + col];
            acc0.x += v.x; acc0.y += v.y; acc0.z += v.z; acc0.w += v.w;
        }
    }
    float4 acc;
    acc.x = (acc0.x + acc1.x) + (acc2.x + acc3.x);
    acc.y = (acc0.y + acc1.y) + (acc2.y + acc3.y);
    acc.z = (acc0.z + acc1.z) + (acc2.z + acc3.z);
    acc.w = (acc0.w + acc1.w) + (acc2.w + acc3.w);
    *(float4*)&g_agg2[w * 128 + col] = acc;
}

// h2 = relu(agg2 @ W2 + b2); graph_embedding += per-block partial sum.
// Block tile: 64 nodes x 256 cols; thread tile: 16 nodes x 4 cols.
__global__ void __launch_bounds__(256) k_h2sum(const float* __restrict__ W2,
                                               const float* __restrict__ b2,
                                               const int* __restrict__ np) {
    int N = get_N(np);
    int base = blockIdx.x * 64;
    if (base >= N) return;

    __shared__ float s_a[64 * 128];   // 32 KB
    __shared__ float s_ge[256];

    int t = threadIdx.x;
    s_ge[t] = 0.0f;

    // load agg2 tile (zero-padded past N): 2048 float4s, 8 per thread
    for (int i = t; i < 64 * 128 / 4; i += 256) {
        int n = base + (i >> 5);
        float4 v = make_float4(0.f, 0.f, 0.f, 0.f);
        if (n < N) v = *(const float4*)&g_agg2[n * 128 + (i & 31) * 4];
        *(float4*)&s_a[i * 4] = v;
    }
    __syncthreads();

    int jg = t & 63;   // column group (4 cols)
    int mg = t >> 6;   // node group (16 nodes)

    float acc[16][4];
#pragma unroll
    for (int m = 0; m < 16; m++)
#pragma unroll
        for (int c = 0; c < 4; c++) acc[m][c] = 0.0f;

    const float* sa = &s_a[mg * 16 * 128];
    for (int k = 0; k < 128; k++) {
        float4 wv = *(const float4*)&W2[k * 256 + jg * 4];
#pragma unroll
        for (int m = 0; m < 16; m++) {
            float a = sa[m * 128 + k];
            acc[m][0] = fmaf(a, wv.x, acc[m][0]);
            acc[m][1] = fmaf(a, wv.y, acc[m][1]);
            acc[m][2] = fmaf(a, wv.z, acc[m][2]);
            acc[m][3] = fmaf(a, wv.w, acc[m][3]);
        }
    }

    float4 bb = *(const float4*)&b2[jg * 4];
    float p0 = 0.f, p1 = 0.f, p2 = 0.f, p3 = 0.f;
#pragma unroll
    for (int m = 0; m < 16; m++) {
        if (base + mg * 16 + m < N) {
            p0 += fmaxf(acc[m][0] + bb.x, 0.0f);
            p1 += fmaxf(acc[m][1] + bb.y, 0.0f);
            p2 += fmaxf(acc[m][2] + bb.z, 0.0f);
            p3 += fmaxf(acc[m][3] + bb.w, 0.0f);
        }
    }
    atomicAdd(&s_ge[jg * 4 + 0], p0);
    atomicAdd(&s_ge[jg * 4 + 1], p1);
    atomicAdd(&s_ge[jg * 4 + 2], p2);
    atomicAdd(&s_ge[jg * 4 + 3], p3);
    __syncthreads();
    atomicAdd(&g_ge[t], s_ge[t]);
}

// final MLP + output write
__global__ void k_final(const float* __restrict__ Wp1, const float* __restrict__ bp1,
                        const float* __restrict__ Wp2, const float* __restrict__ bp2,
                        float* __restrict__ out) {
    __shared__ float s_ge[256];
    __shared__ float s_m[128];
    int t = threadIdx.x;
    float ge = g_ge[t];
    s_ge[t] = ge;
    out[t] = ge;
    __syncthreads();
    if (t < 128) {
        float acc = bp1[t];
        for (int k = 0; k < 256; k++)
            acc = fmaf(s_ge[k], __ldg(&Wp1[k * 128 + t]), acc);
        s_m[t] = fmaxf(acc, 0.0f) * __ldg(&Wp2[t]);
    }
    __syncthreads();
    for (int off = 64; off >= 1; off >>= 1) {
        if (t < off) s_m[t] += s_m[t + off];
        __syncthreads();
    }
    if (t == 0) out[256] = s_m[0] + bp2[0];
}

// ---------------------------------------------------------------------------
extern "C" void kernel_launch(void* const* d_in, const int* in_sizes, int n_in,
                              void* d_out, int out_size) {
    const float* W1  = (const float*)d_in[0];
    const float* b1  = (const float*)d_in[1];
    const float* W2  = (const float*)d_in[2];
    const float* b2  = (const float*)d_in[3];
    const float* Wp1 = (const float*)d_in[4];
    const float* bp1 = (const float*)d_in[5];
    const float* Wp2 = (const float*)d_in[6];
    const float* bp2 = (const float*)d_in[7];
    const int*   src = (const int*)d_in[8];
    const int*   dst = (const int*)d_in[9];
    const int*   np  = (n_in > 10) ? (const int*)d_in[10] : nullptr;
    int E = in_sizes[8];

    int eb4 = (E / 4 + NTHREADS - 1) / NTHREADS + 1;
    k_zero<<<64, NTHREADS>>>();
    k_count<<<eb4, NTHREADS>>>(src, dst, E);
    k_scan<<<1, 1024>>>();
    k_fill<<<eb4, NTHREADS>>>(src, dst, E);
    k_l1<<<(MAXN * 32 + NTHREADS - 1) / NTHREADS, NTHREADS>>>(W1, b1, np);
    k_agg2<<<(MAXN * 32 + NTHREADS - 1) / NTHREADS, NTHREADS>>>(np);
    k_h2sum<<<MAXN / 64, NTHREADS>>>(W2, b2, np);
    k_final<<<1, NTHREADS>>>(Wp1, bp1, Wp2, bp2, (float*)d_out);
    (void)out_size; (void)n_in;
}

// round 4
// speedup vs baseline: 1.1795x; 1.1795x over previous
#include <cuda_runtime.h>

// ---------------------------------------------------------------------------
// MetricPredictor: 2-layer GCN (degree features) + sum-pool + 2-layer MLP
// CSR-gather; layer-1 hidden recomputed from 2 scalars per edge (8B gather
// instead of 512B), eliminating the wide h1 gather entirely.
// ---------------------------------------------------------------------------

#define MAXN 16384
#define MAXE 524288
#define NTHREADS 256
#define FULLMASK 0xFFFFFFFFu

__device__ __align__(16) int   g_incnt[MAXN];
__device__ __align__(16) int   g_outcnt[MAXN];
__device__ __align__(16) int   g_rowoff[MAXN + 1];
__device__ __align__(16) int   g_cursor[MAXN];
__device__ __align__(16) int   g_csrc[MAXE];
__device__ __align__(16) float g_a[2 * MAXN];       // agg1 pairs (a0,a1)
__device__ __align__(16) float g_agg2[MAXN * 128];
__device__ __align__(16) float g_ge[256];

__device__ __forceinline__ int get_N(const int* np) {
    return np ? __ldg(np) : 10000;
}

// ---------------------------------------------------------------------------
__global__ void k_zero() {
    int i = blockIdx.x * blockDim.x + threadIdx.x;
    int stride = gridDim.x * blockDim.x;
    for (int j = i; j < MAXN; j += stride) { g_incnt[j] = 0; g_outcnt[j] = 0; }
    if (i < 256) g_ge[i] = 0.f;
}

// degree counts (1 edge/thread, big grid — round-2 known-good shape)
__global__ void k_count(const int* __restrict__ src, const int* __restrict__ dst, int E) {
    int e = blockIdx.x * blockDim.x + threadIdx.x;
    if (e >= E) return;
    atomicAdd(&g_incnt[dst[e]], 1);
    atomicAdd(&g_outcnt[src[e]], 1);
}

// exclusive scan of g_incnt -> g_rowoff, g_cursor (single block)
__global__ void __launch_bounds__(1024) k_scan() {
    __shared__ int s_part[1024];
    const int CH = MAXN / 1024;  // 16
    int t = threadIdx.x;
    int base = t * CH;
    int loc[CH];
    int sum = 0;
#pragma unroll
    for (int i = 0; i < CH; i++) { loc[i] = sum; sum += g_incnt[base + i]; }
    s_part[t] = sum;
    __syncthreads();
    for (int off = 1; off < 1024; off <<= 1) {
        int v = (t >= off) ? s_part[t - off] : 0;
        __syncthreads();
        s_part[t] += v;
        __syncthreads();
    }
    int pre = (t > 0) ? s_part[t - 1] : 0;
#pragma unroll
    for (int i = 0; i < CH; i++) {
        int o = pre + loc[i];
        g_rowoff[base + i] = o;
        g_cursor[base + i] = o;
    }
    if (t == 1023) g_rowoff[MAXN] = s_part[1023];
}

// fill CSR (1 edge/thread — round-2 known-good shape)
__global__ void k_fill(const int* __restrict__ src, const int* __restrict__ dst, int E) {
    int e = blockIdx.x * blockDim.x + threadIdx.x;
    if (e >= E) return;
    int pos = atomicAdd(&g_cursor[dst[e]], 1);
    g_csrc[pos] = src[e];
}

// agg1 pairs: g_a[n] = sum over in-neighbors s of (in_deg[s], out_deg[s])
__global__ void k_aggpair(const int* __restrict__ np) {
    int N = get_N(np);
    int w = (blockIdx.x * blockDim.x + threadIdx.x) >> 5;
    if (w >= N) return;
    int lane = threadIdx.x & 31;
    int beg = g_rowoff[w];
    int end = beg + g_incnt[w];
    float a0 = 0.f, a1 = 0.f;
    for (int j = beg + lane; j < end; j += 32) {
        int s = g_csrc[j];
        a0 += (float)__ldg(&g_incnt[s]);
        a1 += (float)__ldg(&g_outcnt[s]);
    }
#pragma unroll
    for (int off = 16; off >= 1; off >>= 1) {
        a0 += __shfl_down_sync(FULLMASK, a0, off);
        a1 += __shfl_down_sync(FULLMASK, a1, off);
    }
    if (lane == 0) {
        g_a[2 * w + 0] = a0;
        g_a[2 * w + 1] = a1;
    }
}

// agg2[d] = sum over in-neighbors s of relu(a0[s]*W1[0] + a1[s]*W1[1] + b1)
// One warp per node d; lane owns 4 columns (W1 cols in registers).
// Per edge: one uniform 8B load + 8 FMA + 4 max + 4 add per lane.
__global__ void k_agg2(const float* __restrict__ W1, const float* __restrict__ b1,
                       const int* __restrict__ np) {
    int N = get_N(np);
    int w = (blockIdx.x * blockDim.x + threadIdx.x) >> 5;
    if (w >= N) return;
    int lane = threadIdx.x & 31;
    int j = lane * 4;
    float4 w0 = *(const float4*)&W1[j];         // W1[0][j..j+3]
    float4 w1 = *(const float4*)&W1[128 + j];   // W1[1][j..j+3]
    float4 bb = *(const float4*)&b1[j];

    int beg = g_rowoff[w];
    int end = beg + g_incnt[w];

    float4 acc0 = make_float4(0.f, 0.f, 0.f, 0.f);
    float4 acc1 = acc0, acc2 = acc0, acc3 = acc0;

    int k = beg;
    for (; k + 4 <= end; k += 4) {
        int s0 = __ldg(&g_csrc[k + 0]);
        int s1 = __ldg(&g_csrc[k + 1]);
        int s2 = __ldg(&g_csrc[k + 2]);
        int s3 = __ldg(&g_csrc[k + 3]);
        float2 p0 = *(const float2*)&g_a[2 * s0];
        float2 p1 = *(const float2*)&g_a[2 * s1];
        float2 p2 = *(const float2*)&g_a[2 * s2];
        float2 p3 = *(const float2*)&g_a[2 * s3];
        acc0.x += fmaxf(fmaf(p0.x, w0.x, fmaf(p0.y, w1.x, bb.x)), 0.f);
        acc0.y += fmaxf(fmaf(p0.x, w0.y, fmaf(p0.y, w1.y, bb.y)), 0.f);
        acc0.z += fmaxf(fmaf(p0.x, w0.z, fmaf(p0.y, w1.z, bb.z)), 0.f);
        acc0.w += fmaxf(fmaf(p0.x, w0.w, fmaf(p0.y, w1.w, bb.w)), 0.f);
        acc1.x += fmaxf(fmaf(p1.x, w0.x, fmaf(p1.y, w1.x, bb.x)), 0.f);
        acc1.y += fmaxf(fmaf(p1.x, w0.y, fmaf(p1.y, w1.y, bb.y)), 0.f);
        acc1.z += fmaxf(fmaf(p1.x, w0.z, fmaf(p1.y, w1.z, bb.z)), 0.f);
        acc1.w += fmaxf(fmaf(p1.x, w0.w, fmaf(p1.y, w1.w, bb.w)), 0.f);
        acc2.x += fmaxf(fmaf(p2.x, w0.x, fmaf(p2.y, w1.x, bb.x)), 0.f);
        acc2.y += fmaxf(fmaf(p2.x, w0.y, fmaf(p2.y, w1.y, bb.y)), 0.f);
        acc2.z += fmaxf(fmaf(p2.x, w0.z, fmaf(p2.y, w1.z, bb.z)), 0.f);
        acc2.w += fmaxf(fmaf(p2.x, w0.w, fmaf(p2.y, w1.w, bb.w)), 0.f);
        acc3.x += fmaxf(fmaf(p3.x, w0.x, fmaf(p3.y, w1.x, bb.x)), 0.f);
        acc3.y += fmaxf(fmaf(p3.x, w0.y, fmaf(p3.y, w1.y, bb.y)), 0.f);
        acc3.z += fmaxf(fmaf(p3.x, w0.z, fmaf(p3.y, w1.z, bb.z)), 0.f);
        acc3.w += fmaxf(fmaf(p3.x, w0.w, fmaf(p3.y, w1.w, bb.w)), 0.f);
    }
    for (; k < end; k++) {
        int s = __ldg(&g_csrc[k]);
        float2 p = *(const float2*)&g_a[2 * s];
        acc0.x += fmaxf(fmaf(p.x, w0.x, fmaf(p.y, w1.x, bb.x)), 0.f);
        acc0.y += fmaxf(fmaf(p.x, w0.y, fmaf(p.y, w1.y, bb.y)), 0.f);
        acc0.z += fmaxf(fmaf(p.x, w0.z, fmaf(p.y, w1.z, bb.z)), 0.f);
        acc0.w += fmaxf(fmaf(p.x, w0.w, fmaf(p.y, w1.w, bb.w)), 0.f);
    }
    float4 acc;
    acc.x = (acc0.x + acc1.x) + (acc2.x + acc3.x);
    acc.y = (acc0.y + acc1.y) + (acc2.y + acc3.y);
    acc.z = (acc0.z + acc1.z) + (acc2.z + acc3.z);
    acc.w = (acc0.w + acc1.w) + (acc2.w + acc3.w);
    *(float4*)&g_agg2[w * 128 + j] = acc;
}

// h2 = relu(agg2 @ W2 + b2); graph_embedding += per-block partial sum.
// Block tile: 32 nodes x 256 cols; thread tile: 8 nodes x 4 cols (round-2 form).
__global__ void __launch_bounds__(256) k_h2sum(const float* __restrict__ W2,
                                               const float* __restrict__ b2,
                                               const int* __restrict__ np) {
    int N = get_N(np);
    int base = blockIdx.x * 32;
    if (base >= N) return;

    __shared__ float s_a[32 * 128];
    __shared__ float s_ge[256];

    int t = threadIdx.x;
    s_ge[t] = 0.0f;

    for (int i = t; i < 32 * 128 / 4; i += 256) {
        int n = base + (i >> 5);
        float4 v = make_float4(0.f, 0.f, 0.f, 0.f);
        if (n < N) v = *(const float4*)&g_agg2[n * 128 + (i & 31) * 4];
        *(float4*)&s_a[i * 4] = v;
    }
    __syncthreads();

    int jg = t & 63;
    int mg = t >> 6;

    float acc[8][4];
#pragma unroll
    for (int m = 0; m < 8; m++)
#pragma unroll
        for (int c = 0; c < 4; c++) acc[m][c] = 0.0f;

    const float* sa = &s_a[mg * 8 * 128];
    for (int k = 0; k < 128; k++) {
        float4 wv = *(const float4*)&W2[k * 256 + jg * 4];
#pragma unroll
        for (int m = 0; m < 8; m++) {
            float a = sa[m * 128 + k];
            acc[m][0] = fmaf(a, wv.x, acc[m][0]);
            acc[m][1] = fmaf(a, wv.y, acc[m][1]);
            acc[m][2] = fmaf(a, wv.z, acc[m][2]);
            acc[m][3] = fmaf(a, wv.w, acc[m][3]);
        }
    }

    float4 bb = *(const float4*)&b2[jg * 4];
    float p0 = 0.f, p1 = 0.f, p2 = 0.f, p3 = 0.f;
#pragma unroll
    for (int m = 0; m < 8; m++) {
        if (base + mg * 8 + m < N) {
            p0 += fmaxf(acc[m][0] + bb.x, 0.0f);
            p1 += fmaxf(acc[m][1] + bb.y, 0.0f);
            p2 += fmaxf(acc[m][2] + bb.z, 0.0f);
            p3 += fmaxf(acc[m][3] + bb.w, 0.0f);
        }
    }
    atomicAdd(&s_ge[jg * 4 + 0], p0);
    atomicAdd(&s_ge[jg * 4 + 1], p1);
    atomicAdd(&s_ge[jg * 4 + 2], p2);
    atomicAdd(&s_ge[jg * 4 + 3], p3);
    __syncthreads();
    atomicAdd(&g_ge[t], s_ge[t]);
}

// final MLP + output write
__global__ void k_final(const float* __restrict__ Wp1, const float* __restrict__ bp1,
                        const float* __restrict__ Wp2, const float* __restrict__ bp2,
                        float* __restrict__ out) {
    __shared__ float s_ge[256];
    __shared__ float s_m[128];
    int t = threadIdx.x;
    float ge = g_ge[t];
    s_ge[t] = ge;
    out[t] = ge;
    __syncthreads();
    if (t < 128) {
        float acc = bp1[t];
        for (int k = 0; k < 256; k++)
            acc = fmaf(s_ge[k], __ldg(&Wp1[k * 128 + t]), acc);
        s_m[t] = fmaxf(acc, 0.0f) * __ldg(&Wp2[t]);
    }
    __syncthreads();
    for (int off = 64; off >= 1; off >>= 1) {
        if (t < off) s_m[t] += s_m[t + off];
        __syncthreads();
    }
    if (t == 0) out[256] = s_m[0] + bp2[0];
}

// ---------------------------------------------------------------------------
extern "C" void kernel_launch(void* const* d_in, const int* in_sizes, int n_in,
                              void* d_out, int out_size) {
    const float* W1  = (const float*)d_in[0];
    const float* b1  = (const float*)d_in[1];
    const float* W2  = (const float*)d_in[2];
    const float* b2  = (const float*)d_in[3];
    const float* Wp1 = (const float*)d_in[4];
    const float* bp1 = (const float*)d_in[5];
    const float* Wp2 = (const float*)d_in[6];
    const float* bp2 = (const float*)d_in[7];
    const int*   src = (const int*)d_in[8];
    const int*   dst = (const int*)d_in[9];
    const int*   np  = (n_in > 10) ? (const int*)d_in[10] : nullptr;
    int E = in_sizes[8];

    int eb = (E + NTHREADS - 1) / NTHREADS;
    k_zero<<<64, NTHREADS>>>();
    k_count<<<eb, NTHREADS>>>(src, dst, E);
    k_scan<<<1, 1024>>>();
    k_fill<<<eb, NTHREADS>>>(src, dst, E);
    k_aggpair<<<(MAXN * 32 + NTHREADS - 1) / NTHREADS, NTHREADS>>>(np);
    k_agg2<<<(MAXN * 32 + NTHREADS - 1) / NTHREADS, NTHREADS>>>(W1, b1, np);
    k_h2sum<<<MAXN / 32, NTHREADS>>>(W2, b2, np);
    k_final<<<1, NTHREADS>>>(Wp1, bp1, Wp2, bp2, (float*)d_out);
    (void)out_size; (void)n_in;
}

// round 5
// speedup vs baseline: 1.3054x; 1.1067x over previous
#include <cuda_runtime.h>

// ---------------------------------------------------------------------------
// MetricPredictor: 2-layer GCN (degree features) + sum-pool + 2-layer MLP
// CSR-gather; 6 graph nodes: count, scan, fill, aggpair, agg2, h2sum+final.
// Cross-replay invariant: g_incnt/g_outcnt are zero at kernel_launch entry
// (zero-initialized at load; re-zeroed by the last block of h2sum each call).
// ---------------------------------------------------------------------------

#define MAXN 16384
#define MAXE 524288
#define NTHREADS 256
#define FULLMASK 0xFFFFFFFFu
#define H2_GRID (MAXN / 32)   // 512 blocks

__device__ __align__(16) int   g_incnt[MAXN];
__device__ __align__(16) int   g_outcnt[MAXN];
__device__ __align__(16) int   g_rowoff[MAXN + 1];
__device__ __align__(16) int   g_cursor[MAXN];
__device__ __align__(16) int   g_csrc[MAXE];
__device__ __align__(16) float g_a[2 * MAXN];       // agg1 pairs (a0,a1)
__device__ __align__(16) float g_agg2[MAXN * 128];
__device__ __align__(16) float g_ge[256];
__device__ int g_done;

__device__ __forceinline__ int get_N(const int* np) {
    return np ? __ldg(np) : 10000;
}

// ---------------------------------------------------------------------------
// degree counts: 2 edges/thread, int2 loads, 4 independent REDG
__global__ void k_count(const int* __restrict__ src, const int* __restrict__ dst, int E) {
    int i = blockIdx.x * blockDim.x + threadIdx.x;
    int e0 = 2 * i;
    if (e0 + 1 < E) {
        int2 s = *(const int2*)&src[e0];
        int2 d = *(const int2*)&dst[e0];
        atomicAdd(&g_incnt[d.x], 1);
        atomicAdd(&g_incnt[d.y], 1);
        atomicAdd(&g_outcnt[s.x], 1);
        atomicAdd(&g_outcnt[s.y], 1);
    } else if (e0 < E) {
        atomicAdd(&g_incnt[dst[e0]], 1);
        atomicAdd(&g_outcnt[src[e0]], 1);
    }
}

// exclusive scan of g_incnt -> g_rowoff, g_cursor; also zeroes g_ge/g_done
__global__ void __launch_bounds__(1024) k_scan() {
    __shared__ int s_part[1024];
    const int CH = MAXN / 1024;  // 16
    int t = threadIdx.x;
    int base = t * CH;
    int loc[CH];
    int sum = 0;
#pragma unroll
    for (int i = 0; i < CH; i++) { loc[i] = sum; sum += g_incnt[base + i]; }
    s_part[t] = sum;
    __syncthreads();
    for (int off = 1; off < 1024; off <<= 1) {
        int v = (t >= off) ? s_part[t - off] : 0;
        __syncthreads();
        s_part[t] += v;
        __syncthreads();
    }
    int pre = (t > 0) ? s_part[t - 1] : 0;
#pragma unroll
    for (int i = 0; i < CH; i++) {
        int o = pre + loc[i];
        g_rowoff[base + i] = o;
        g_cursor[base + i] = o;
    }
    if (t == 1023) g_rowoff[MAXN] = s_part[1023];
    if (t < 256) g_ge[t] = 0.0f;
    if (t == 0) g_done = 0;
}

// fill CSR (1 edge/thread — measured-good shape)
__global__ void k_fill(const int* __restrict__ src, const int* __restrict__ dst, int E) {
    int e = blockIdx.x * blockDim.x + threadIdx.x;
    if (e >= E) return;
    int pos = atomicAdd(&g_cursor[dst[e]], 1);
    g_csrc[pos] = src[e];
}

// agg1 pairs: g_a[n] = sum over in-neighbors s of (in_deg[s], out_deg[s])
__global__ void k_aggpair(const int* __restrict__ np) {
    int N = get_N(np);
    int w = (blockIdx.x * blockDim.x + threadIdx.x) >> 5;
    if (w >= N) return;
    int lane = threadIdx.x & 31;
    int beg = g_rowoff[w];
    int end = beg + g_incnt[w];
    float a0 = 0.f, a1 = 0.f;
    for (int j = beg + lane; j < end; j += 32) {
        int s = g_csrc[j];
        a0 += (float)__ldg(&g_incnt[s]);
        a1 += (float)__ldg(&g_outcnt[s]);
    }
#pragma unroll
    for (int off = 16; off >= 1; off >>= 1) {
        a0 += __shfl_down_sync(FULLMASK, a0, off);
        a1 += __shfl_down_sync(FULLMASK, a1, off);
    }
    if (lane == 0) {
        g_a[2 * w + 0] = a0;
        g_a[2 * w + 1] = a1;
    }
}

// agg2[d] = sum over in-neighbors s of relu(a0[s]*W1[0] + a1[s]*W1[1] + b1)
__global__ void k_agg2(const float* __restrict__ W1, const float* __restrict__ b1,
                       const int* __restrict__ np) {
    int N = get_N(np);
    int w = (blockIdx.x * blockDim.x + threadIdx.x) >> 5;
    if (w >= N) return;
    int lane = threadIdx.x & 31;
    int j = lane * 4;
    float4 w0 = *(const float4*)&W1[j];
    float4 w1 = *(const float4*)&W1[128 + j];
    float4 bb = *(const float4*)&b1[j];

    int beg = g_rowoff[w];
    int end = beg + g_incnt[w];

    float4 acc0 = make_float4(0.f, 0.f, 0.f, 0.f);
    float4 acc1 = acc0, acc2 = acc0, acc3 = acc0;

    int k = beg;
    for (; k + 4 <= end; k += 4) {
        int s0 = __ldg(&g_csrc[k + 0]);
        int s1 = __ldg(&g_csrc[k + 1]);
        int s2 = __ldg(&g_csrc[k + 2]);
        int s3 = __ldg(&g_csrc[k + 3]);
        float2 p0 = *(const float2*)&g_a[2 * s0];
        float2 p1 = *(const float2*)&g_a[2 * s1];
        float2 p2 = *(const float2*)&g_a[2 * s2];
        float2 p3 = *(const float2*)&g_a[2 * s3];
        acc0.x += fmaxf(fmaf(p0.x, w0.x, fmaf(p0.y, w1.x, bb.x)), 0.f);
        acc0.y += fmaxf(fmaf(p0.x, w0.y, fmaf(p0.y, w1.y, bb.y)), 0.f);
        acc0.z += fmaxf(fmaf(p0.x, w0.z, fmaf(p0.y, w1.z, bb.z)), 0.f);
        acc0.w += fmaxf(fmaf(p0.x, w0.w, fmaf(p0.y, w1.w, bb.w)), 0.f);
        acc1.x += fmaxf(fmaf(p1.x, w0.x, fmaf(p1.y, w1.x, bb.x)), 0.f);
        acc1.y += fmaxf(fmaf(p1.x, w0.y, fmaf(p1.y, w1.y, bb.y)), 0.f);
        acc1.z += fmaxf(fmaf(p1.x, w0.z, fmaf(p1.y, w1.z, bb.z)), 0.f);
        acc1.w += fmaxf(fmaf(p1.x, w0.w, fmaf(p1.y, w1.w, bb.w)), 0.f);
        acc2.x += fmaxf(fmaf(p2.x, w0.x, fmaf(p2.y, w1.x, bb.x)), 0.f);
        acc2.y += fmaxf(fmaf(p2.x, w0.y, fmaf(p2.y, w1.y, bb.y)), 0.f);
        acc2.z += fmaxf(fmaf(p2.x, w0.z, fmaf(p2.y, w1.z, bb.z)), 0.f);
        acc2.w += fmaxf(fmaf(p2.x, w0.w, fmaf(p2.y, w1.w, bb.w)), 0.f);
        acc3.x += fmaxf(fmaf(p3.x, w0.x, fmaf(p3.y, w1.x, bb.x)), 0.f);
        acc3.y += fmaxf(fmaf(p3.x, w0.y, fmaf(p3.y, w1.y, bb.y)), 0.f);
        acc3.z += fmaxf(fmaf(p3.x, w0.z, fmaf(p3.y, w1.z, bb.z)), 0.f);
        acc3.w += fmaxf(fmaf(p3.x, w0.w, fmaf(p3.y, w1.w, bb.w)), 0.f);
    }
    for (; k < end; k++) {
        int s = __ldg(&g_csrc[k]);
        float2 p = *(const float2*)&g_a[2 * s];
        acc0.x += fmaxf(fmaf(p.x, w0.x, fmaf(p.y, w1.x, bb.x)), 0.f);
        acc0.y += fmaxf(fmaf(p.x, w0.y, fmaf(p.y, w1.y, bb.y)), 0.f);
        acc0.z += fmaxf(fmaf(p.x, w0.z, fmaf(p.y, w1.z, bb.z)), 0.f);
        acc0.w += fmaxf(fmaf(p.x, w0.w, fmaf(p.y, w1.w, bb.w)), 0.f);
    }
    float4 acc;
    acc.x = (acc0.x + acc1.x) + (acc2.x + acc3.x);
    acc.y = (acc0.y + acc1.y) + (acc2.y + acc3.y);
    acc.z = (acc0.z + acc1.z) + (acc2.z + acc3.z);
    acc.w = (acc0.w + acc1.w) + (acc2.w + acc3.w);
    *(float4*)&g_agg2[w * 128 + j] = acc;
}

// h2 = relu(agg2 @ W2 + b2); embedding accumulation; last block runs the
// final MLP and re-zeroes the count arrays for the next replay.
__global__ void __launch_bounds__(256) k_h2sum(const float* __restrict__ W2,
                                               const float* __restrict__ b2,
                                               const float* __restrict__ Wp1,
                                               const float* __restrict__ bp1,
                                               const float* __restrict__ Wp2,
                                               const float* __restrict__ bp2,
                                               float* __restrict__ out,
                                               const int* __restrict__ np) {
    int N = get_N(np);
    int base = blockIdx.x * 32;
    int t = threadIdx.x;

    __shared__ float s_a[32 * 128];
    __shared__ float s_ge[256];
    __shared__ int s_last;

    if (base < N) {
        s_ge[t] = 0.0f;
        for (int i = t; i < 32 * 128 / 4; i += 256) {
            int n = base + (i >> 5);
            float4 v = make_float4(0.f, 0.f, 0.f, 0.f);
            if (n < N) v = *(const float4*)&g_agg2[n * 128 + (i & 31) * 4];
            *(float4*)&s_a[i * 4] = v;
        }
        __syncthreads();

        int jg = t & 63;
        int mg = t >> 6;

        float acc[8][4];
#pragma unroll
        for (int m = 0; m < 8; m++)
#pragma unroll
            for (int c = 0; c < 4; c++) acc[m][c] = 0.0f;

        const float* sa = &s_a[mg * 8 * 128];
#pragma unroll 4
        for (int k = 0; k < 128; k++) {
            float4 wv = *(const float4*)&W2[k * 256 + jg * 4];
#pragma unroll
            for (int m = 0; m < 8; m++) {
                float a = sa[m * 128 + k];
                acc[m][0] = fmaf(a, wv.x, acc[m][0]);
                acc[m][1] = fmaf(a, wv.y, acc[m][1]);
                acc[m][2] = fmaf(a, wv.z, acc[m][2]);
                acc[m][3] = fmaf(a, wv.w, acc[m][3]);
            }
        }

        float4 bb = *(const float4*)&b2[jg * 4];
        float p0 = 0.f, p1 = 0.f, p2 = 0.f, p3 = 0.f;
#pragma unroll
        for (int m = 0; m < 8; m++) {
            if (base + mg * 8 + m < N) {
                p0 += fmaxf(acc[m][0] + bb.x, 0.0f);
                p1 += fmaxf(acc[m][1] + bb.y, 0.0f);
                p2 += fmaxf(acc[m][2] + bb.z, 0.0f);
                p3 += fmaxf(acc[m][3] + bb.w, 0.0f);
            }
        }
        atomicAdd(&s_ge[jg * 4 + 0], p0);
        atomicAdd(&s_ge[jg * 4 + 1], p1);
        atomicAdd(&s_ge[jg * 4 + 2], p2);
        atomicAdd(&s_ge[jg * 4 + 3], p3);
        __syncthreads();
        atomicAdd(&g_ge[t], s_ge[t]);
    }

    // ---- arrival counter: all gridDim.x blocks participate ----
    __threadfence();
    if (t == 0) {
        int c = atomicAdd(&g_done, 1);
        s_last = (c == (int)gridDim.x - 1);
    }
    __syncthreads();
    if (!s_last) return;

    // ---- final MLP (single block) ----
    __shared__ float f_ge[256];
    __shared__ float f_m[128];
    float ge = g_ge[t];
    f_ge[t] = ge;
    out[t] = ge;
    __syncthreads();
    if (t < 128) {
        float acc = bp1[t];
        for (int k = 0; k < 256; k++)
            acc = fmaf(f_ge[k], __ldg(&Wp1[k * 128 + t]), acc);
        f_m[t] = fmaxf(acc, 0.0f) * __ldg(&Wp2[t]);
    }
    __syncthreads();
    for (int off = 64; off >= 1; off >>= 1) {
        if (t < off) f_m[t] += f_m[t + off];
        __syncthreads();
    }
    if (t == 0) out[256] = f_m[0] + bp2[0];

    // ---- re-zero count arrays for the next replay ----
    for (int i = t; i < MAXN; i += 256) {
        g_incnt[i] = 0;
        g_outcnt[i] = 0;
    }
}

// ---------------------------------------------------------------------------
extern "C" void kernel_launch(void* const* d_in, const int* in_sizes, int n_in,
                              void* d_out, int out_size) {
    const float* W1  = (const float*)d_in[0];
    const float* b1  = (const float*)d_in[1];
    const float* W2  = (const float*)d_in[2];
    const float* b2  = (const float*)d_in[3];
    const float* Wp1 = (const float*)d_in[4];
    const float* bp1 = (const float*)d_in[5];
    const float* Wp2 = (const float*)d_in[6];
    const float* bp2 = (const float*)d_in[7];
    const int*   src = (const int*)d_in[8];
    const int*   dst = (const int*)d_in[9];
    const int*   np  = (n_in > 10) ? (const int*)d_in[10] : nullptr;
    int E = in_sizes[8];

    int eb  = (E + NTHREADS - 1) / NTHREADS;
    int eb2 = (E / 2 + NTHREADS - 1) / NTHREADS + 1;
    k_count<<<eb2, NTHREADS>>>(src, dst, E);
    k_scan<<<1, 1024>>>();
    k_fill<<<eb, NTHREADS>>>(src, dst, E);
    k_aggpair<<<(MAXN * 32 + NTHREADS - 1) / NTHREADS, NTHREADS>>>(np);
    k_agg2<<<(MAXN * 32 + NTHREADS - 1) / NTHREADS, NTHREADS>>>(W1, b1, np);
    k_h2sum<<<H2_GRID, NTHREADS>>>(W2, b2, Wp1, bp1, Wp2, bp2, (float*)d_out, np);
    (void)out_size; (void)n_in;
}